// round 14
// baseline (speedup 1.0000x reference)
#include <cuda_runtime.h>
#include <cuda_bf16.h>
#include <cstdint>
#include <cstddef>

// ---------------- problem constants ----------------
#define BB   256
#define PP   100
#define NN   101
#define EE   256
#define HH   16
#define NE   8
#define TT   (BB*PP)

// ---------------- scratch ----------------
__device__ float g_q  [TT    * EE];
__device__ float g_k  [BB*NN * EE];
__device__ float g_v  [BB*NN * EE];
__device__ float g_att[TT    * EE];
__device__ float g_mh [2*TT  * EE];
__device__ int   g_topi[TT * 2];
__device__ float g_topg[TT * 2];
__device__ int   g_list[NE * TT];
__device__ int   g_count[NE];

// ---------------- bf16 split helpers ----------------
__device__ __forceinline__ void splitpack(float x0, float x1,
                                          uint32_t& h, uint32_t& l)
{
    __nv_bfloat162 hb = __floats2bfloat162_rn(x0, x1);
    float r0 = x0 - __bfloat162float(hb.x);
    float r1 = x1 - __bfloat162float(hb.y);
    __nv_bfloat162 lb = __floats2bfloat162_rn(r0, r1);
    h = *reinterpret_cast<uint32_t*>(&hb);
    l = *reinterpret_cast<uint32_t*>(&lb);
}
__device__ __forceinline__ void mma16(float c[4],
    uint32_t a0, uint32_t a1, uint32_t a2, uint32_t a3,
    uint32_t b0, uint32_t b1)
{
    asm volatile(
        "mma.sync.aligned.m16n8k16.row.col.f32.bf16.bf16.f32 "
        "{%0,%1,%2,%3}, {%4,%5,%6,%7}, {%8,%9}, {%0,%1,%2,%3};"
        : "+f"(c[0]), "+f"(c[1]), "+f"(c[2]), "+f"(c[3])
        : "r"(a0), "r"(a1), "r"(a2), "r"(a3), "r"(b0), "r"(b1));
}

// ============================================================
// bf16x3 GEMM: 128x128 tile, BK=16, 256 threads (8 warps 2x4),
// warp tile 64x32, pitch-12 packed smem, 2-stage double buffer.
// MODE 0: fused k/v proj: y<2 -> Wk->g_k, y>=2 -> Wv->g_v
// MODE 1: q proj, A = concat(eln, attr), K=260
// MODE 2: gathered expert GEMM + gate/bias epilogue
// MODE 3: per-batch pointer scores + bias/tanh/ninf + FUSED
//         output softmax (scores staged in smem) -> d_out
// ============================================================
#define PLANE 1536               // 128 rows * 12 uint32
#define GEMM_SMEM (8 * PLANE * 4 + 1536)
#define SCP 104                  // score buffer pitch (floats)

template<int MODE>
__launch_bounds__(256, 2)
__global__ void gemm_bf16(const float* __restrict__ A,
                          const float* __restrict__ A2,
                          const float* __restrict__ Bm,
                          const float* __restrict__ Bm2,
                          float* __restrict__ Cout,
                          float* __restrict__ Cout2,
                          int M, int K,
                          const int*   __restrict__ list,
                          const int*   __restrict__ count,
                          const float* __restrict__ topg,
                          const float* __restrict__ eb,
                          const float* __restrict__ bias,
                          const float* __restrict__ bias1,
                          const float* __restrict__ ninf)
{
    extern __shared__ uint32_t smemu[];
    uint32_t* Ah = smemu;                // 2 stages x PLANE
    uint32_t* Al = Ah + 2 * PLANE;
    uint32_t* Bh = Al + 2 * PLANE;
    uint32_t* Bl = Bh + 2 * PLANE;
    int*    s_tok  = (int*)  (Bl + 2 * PLANE);
    float*  s_gate = (float*)(s_tok + 128);
    int*    s_slot = (int*)  (s_gate + 128);
    float*  sScore = (float*)smemu;      // MODE 3: reused after mainloop

    const int tid = threadIdx.x;
    const int m0 = blockIdx.x * 128;
    const int bz = blockIdx.z;

    int n0;
    const float* Aro = A;
    const float* Bro;
    float* Co;
    int e = 0;

    if (MODE == 0) {
        int y = blockIdx.y;
        Bro = (y < 2) ? Bm : Bm2;
        Co  = (y < 2) ? Cout : Cout2;
        n0  = (y & 1) * 128;
    } else {
        Bro = Bm; Co = Cout;
        n0 = blockIdx.y * 128;
    }
    if (MODE == 2) {
        e = bz;
        int cnt = count[e];
        if (m0 >= cnt) return;
        Bro = Bm + (size_t)e * 65536;
        if (tid < 128) {
            int r = m0 + tid;
            if (r < cnt) {
                int entry = list[e * TT + r];
                s_tok[tid]  = entry >> 1;
                s_slot[tid] = entry & 1;
                s_gate[tid] = topg[entry];
            } else s_tok[tid] = -1;
        }
        __syncthreads();
    }
    if (MODE == 3) {
        Aro = A  + (size_t)bz * PP * EE;
        Bro = Bm + (size_t)bz * NN * EE;
    }

    const int NT = (MODE == 1) ? 17 : 16;

    const int wid = tid >> 5, lane = tid & 31;
    const int wm = wid & 1;
    const int wn = wid >> 1;
    const int g  = lane >> 2;
    const int tg = lane & 3;

    const int amA[2] = { (0*256 + tid) >> 2, (1*256 + tid) >> 2 };
    const int akc    = tid & 3;
    const int akA    = akc * 4;
    const int bn [2] = { (0*256 + tid) & 127, (1*256 + tid) & 127 };
    const int bkq[2] = { (0*256 + tid) >> 7,  (1*256 + tid) >> 7 };

    float4 av[2], bv[2];

    auto loadA = [&](int k0) {
#pragma unroll
        for (int it = 0; it < 2; it++) {
            int m = amA[it];
            int kg = k0 + akA;
            float4 v = make_float4(0.f, 0.f, 0.f, 0.f);
            if (MODE == 1) {
                if (kg < 256)       v = *(const float4*)(Aro + (size_t)(m0 + m) * 256 + kg);
                else if (kg == 256) v = *(const float4*)(A2 + (size_t)(m0 + m) * 4);
            } else if (MODE == 2) {
                int t = s_tok[m];
                if (t >= 0) v = *(const float4*)(Aro + (size_t)t * 256 + kg);
            } else if (MODE == 3) {
                if (m < PP) {
                    float4 x = *(const float4*)(Aro + (size_t)m * 256 + kg);
                    float4 y = *(const float4*)(Aro + (size_t)TT * EE + (size_t)m * 256 + kg);
                    v = make_float4(x.x + y.x, x.y + y.y, x.z + y.z, x.w + y.w);
                }
            } else {
                v = *(const float4*)(Aro + (size_t)(m0 + m) * 256 + kg);
            }
            av[it] = v;
        }
    };
    auto loadB = [&](int k0) {
#pragma unroll
        for (int it = 0; it < 2; it++) {
            int n = bn[it], kq = bkq[it];
            if (MODE == 3) {
                bv[it] = (n < NN)
                    ? *(const float4*)(Bro + (size_t)n * 256 + k0 + kq * 4)
                    : make_float4(0.f, 0.f, 0.f, 0.f);
            } else {
                float vv[4];
#pragma unroll
                for (int i = 0; i < 4; i++) {
                    int kg = k0 + kq * 4 + i;
                    vv[i] = (kg < K) ? Bro[(size_t)kg * 256 + n0 + n] : 0.f;
                }
                bv[it] = make_float4(vv[0], vv[1], vv[2], vv[3]);
            }
        }
    };
    auto storeTile = [&](int stg) {
        uint32_t* Ahs = Ah + stg * PLANE;
        uint32_t* Als = Al + stg * PLANE;
        uint32_t* Bhs = Bh + stg * PLANE;
        uint32_t* Bls = Bl + stg * PLANE;
#pragma unroll
        for (int it = 0; it < 2; it++) {
            uint32_t h01, l01, h23, l23;
            splitpack(av[it].x, av[it].y, h01, l01);
            splitpack(av[it].z, av[it].w, h23, l23);
            int idx = amA[it] * 12 + akc * 2;
            *(uint2*)&Ahs[idx] = make_uint2(h01, h23);
            *(uint2*)&Als[idx] = make_uint2(l01, l23);
        }
#pragma unroll
        for (int it = 0; it < 2; it++) {
            uint32_t h01, l01, h23, l23;
            splitpack(bv[it].x, bv[it].y, h01, l01);
            splitpack(bv[it].z, bv[it].w, h23, l23);
            int idx = bn[it] * 12 + bkq[it] * 2;
            *(uint2*)&Bhs[idx] = make_uint2(h01, h23);
            *(uint2*)&Bls[idx] = make_uint2(l01, l23);
        }
    };

    float c[4][4][4];
#pragma unroll
    for (int mt = 0; mt < 4; mt++)
#pragma unroll
        for (int nt = 0; nt < 4; nt++)
#pragma unroll
            for (int j = 0; j < 4; j++) c[mt][nt][j] = 0.f;

    loadA(0); loadB(0);
    storeTile(0);
    __syncthreads();

    int cur = 0;
    for (int t = 0; t < NT; t++) {
        if (t + 1 < NT) { loadA((t + 1) * 16); loadB((t + 1) * 16); }

        const uint32_t* Ach = Ah + cur * PLANE;
        const uint32_t* Acl = Al + cur * PLANE;
        const uint32_t* Bch = Bh + cur * PLANE;
        const uint32_t* Bcl = Bl + cur * PLANE;

        uint32_t bhf[4][2], blf[4][2];
#pragma unroll
        for (int nt = 0; nt < 4; nt++) {
            int n = wn * 32 + nt * 8 + g;
            bhf[nt][0] = Bch[n * 12 + tg];
            bhf[nt][1] = Bch[n * 12 + tg + 4];
            blf[nt][0] = Bcl[n * 12 + tg];
            blf[nt][1] = Bcl[n * 12 + tg + 4];
        }
#pragma unroll
        for (int mt = 0; mt < 4; mt++) {
            int r0 = (wm * 64 + mt * 16 + g) * 12;
            int r1 = r0 + 8 * 12;
            uint32_t ah0 = Ach[r0 + tg],     ah1 = Ach[r1 + tg];
            uint32_t ah2 = Ach[r0 + tg + 4], ah3 = Ach[r1 + tg + 4];
            uint32_t al0 = Acl[r0 + tg],     al1 = Acl[r1 + tg];
            uint32_t al2 = Acl[r0 + tg + 4], al3 = Acl[r1 + tg + 4];
#pragma unroll
            for (int nt = 0; nt < 4; nt++)
                mma16(c[mt][nt], ah0, ah1, ah2, ah3, bhf[nt][0], bhf[nt][1]);
#pragma unroll
            for (int nt = 0; nt < 4; nt++)
                mma16(c[mt][nt], al0, al1, al2, al3, bhf[nt][0], bhf[nt][1]);
#pragma unroll
            for (int nt = 0; nt < 4; nt++)
                mma16(c[mt][nt], ah0, ah1, ah2, ah3, blf[nt][0], blf[nt][1]);
        }
        if (t + 1 < NT) {
            storeTile(cur ^ 1);
            __syncthreads();
            cur ^= 1;
        }
    }

    if (MODE == 3) __syncthreads();   // smem about to be reused for scores

    // ---------- epilogue ----------
#pragma unroll
    for (int mt = 0; mt < 4; mt++) {
#pragma unroll
        for (int nt = 0; nt < 4; nt++) {
            int ml = wm * 64 + mt * 16 + g;
            int nl = wn * 32 + nt * 8 + tg * 2;
#pragma unroll
            for (int half = 0; half < 2; half++) {
                int row = ml + half * 8;
                float v0 = c[mt][nt][half * 2 + 0];
                float v1 = c[mt][nt][half * 2 + 1];
                if (MODE <= 1) {
                    *(float2*)(Co + (size_t)(m0 + row) * 256 + n0 + nl) =
                        make_float2(v0, v1);
                } else if (MODE == 2) {
                    int t = s_tok[row];
                    if (t >= 0) {
                        float gate = s_gate[row];
                        const float* bb = eb + e * 256 + n0 + nl;
                        *(float2*)(Co + (size_t)s_slot[row] * TT * EE +
                                   (size_t)t * 256 + n0 + nl) =
                            make_float2(gate * (v0 + bb[0]), gate * (v1 + bb[1]));
                    }
                } else {
                    if (row < PP) {
#pragma unroll
                        for (int j = 0; j < 2; j++) {
                            int col = nl + j;
                            if (col < NN) {
                                size_t off = (size_t)bz * PP * NN + (size_t)row * NN + col;
                                float s = (j ? v1 : v0) + bias[off] + bias1[off];
                                s = 10.f * tanhf(s * 0.0625f);
                                sScore[row * SCP + col] = s + ninf[off];
                            }
                        }
                    }
                }
            }
        }
    }

    // ---------- MODE 3: fused output softmax ----------
    if (MODE == 3) {
        __syncthreads();
        float* outb = Co + (size_t)bz * PP * NN;
        for (int r = wid; r < PP; r += 8) {
            const float* srow = sScore + r * SCP;
            float vals[4];
            float mx = -1e30f;
#pragma unroll
            for (int i = 0; i < 4; i++) {
                int n = lane + i * 32;
                vals[i] = (n < NN) ? srow[n] : -1e30f;
                mx = fmaxf(mx, vals[i]);
            }
#pragma unroll
            for (int o = 16; o; o >>= 1) mx = fmaxf(mx, __shfl_xor_sync(~0u, mx, o));
            float sum = 0.f;
#pragma unroll
            for (int i = 0; i < 4; i++) {
                vals[i] = __expf(vals[i] - mx);
                sum += vals[i];
            }
#pragma unroll
            for (int o = 16; o; o >>= 1) sum += __shfl_xor_sync(~0u, sum, o);
            float inv = 1.f / sum;
#pragma unroll
            for (int i = 0; i < 4; i++) {
                int n = lane + i * 32;
                if (n < NN) outb[r * NN + n] = vals[i] * inv;
            }
        }
    }
}

// ============================================================
// Attention: block (b,h), 128 threads. Thread-QUAD owns 4 rows
// {p, p+25, p+50, p+75}; quad splits the n loop in quarters.
// Each K/V smem fetch serves 4 rows (LDS traffic halved vs R13).
// q: each thread loads only its own row; quad assembles via shfl.
// Fused softmax: exp+sum merged into PV pass.
// ============================================================
#define SH4(dst, s, src) \
    dst.x = __shfl_sync(am, s.x, src); dst.y = __shfl_sync(am, s.y, src); \
    dst.z = __shfl_sync(am, s.z, src); dst.w = __shfl_sync(am, s.w, src);

__global__ __launch_bounds__(128)
void attn_kernel(const float* __restrict__ q,
                 const float* __restrict__ k,
                 const float* __restrict__ v,
                 const float* __restrict__ ninf,
                 float* __restrict__ outc)
{
    extern __shared__ float sm[];
    float* sS = sm;                  // 10100
    float* sK = sm + 10100;          // 1616
    float* sV = sm + 10100 + 1616;   // 1616
    const int b = blockIdx.x, h = blockIdx.y;
    const int tid = threadIdx.x;

    const float4* nf4 = (const float4*)(ninf + (size_t)b * PP * NN);
    float4* sS4 = (float4*)sS;
    for (int i = tid; i < PP * NN / 4; i += 128) sS4[i] = nf4[i];

    const float* kb = k + (size_t)b * NN * EE + h * 16;
    const float* vb = v + (size_t)b * NN * EE + h * 16;
    for (int i = tid; i < NN * 4; i += 128) {
        int n = i >> 2, c = i & 3;
        *(float4*)(sK + n * 16 + c * 4) = *(const float4*)(kb + (size_t)n * EE + c * 4);
        *(float4*)(sV + n * 16 + c * 4) = *(const float4*)(vb + (size_t)n * EE + c * 4);
    }
    __syncthreads();

    const int pg = tid >> 2, qr = tid & 3;
    if (pg < 25) {
        unsigned am = __activemask();
        const int lane = tid & 31;
        const int lbase = lane & ~3;

        // own q row, then assemble the quad's 4 rows via shfl
        const int rown = pg + 25 * qr;
        const float* qp = q + ((size_t)b * PP + rown) * EE + h * 16;
        float4 my0 = ((const float4*)qp)[0];
        float4 my1 = ((const float4*)qp)[1];
        float4 my2 = ((const float4*)qp)[2];
        float4 my3 = ((const float4*)qp)[3];
        float4 qv[4][4];
#pragma unroll
        for (int j = 0; j < 4; j++) {
            int src = lbase + j;
            SH4(qv[j][0], my0, src)
            SH4(qv[j][1], my1, src)
            SH4(qv[j][2], my2, src)
            SH4(qv[j][3], my3, src)
        }

        const int QB[5] = {0, 26, 51, 76, 101};
        const int nbeg = QB[qr], nend = QB[qr + 1];

        // pass 1: scores + per-row max
        float mx[4] = {-1e30f, -1e30f, -1e30f, -1e30f};
        for (int n = nbeg; n < nend; n++) {
            const float4* kk4 = (const float4*)(sK + n * 16);
            float4 k0 = kk4[0], k1 = kk4[1], k2 = kk4[2], k3 = kk4[3];
#pragma unroll
            for (int j = 0; j < 4; j++) {
                float s = qv[j][0].x*k0.x + qv[j][0].y*k0.y + qv[j][0].z*k0.z + qv[j][0].w*k0.w
                        + qv[j][1].x*k1.x + qv[j][1].y*k1.y + qv[j][1].z*k1.z + qv[j][1].w*k1.w
                        + qv[j][2].x*k2.x + qv[j][2].y*k2.y + qv[j][2].z*k2.z + qv[j][2].w*k2.w
                        + qv[j][3].x*k3.x + qv[j][3].y*k3.y + qv[j][3].z*k3.z + qv[j][3].w*k3.w;
                float* rp = sS + (pg + 25 * j) * NN + n;
                float val = s * 0.25f + *rp;
                *rp = val;
                mx[j] = fmaxf(mx[j], val);
            }
        }
#pragma unroll
        for (int j = 0; j < 4; j++) {
            mx[j] = fmaxf(mx[j], __shfl_xor_sync(am, mx[j], 1));
            mx[j] = fmaxf(mx[j], __shfl_xor_sync(am, mx[j], 2));
        }

        // pass 2 (fused): exp + sum + PV accumulate
        float sum[4] = {0.f, 0.f, 0.f, 0.f};
        float4 oc[4][4];
#pragma unroll
        for (int j = 0; j < 4; j++)
#pragma unroll
            for (int cidx = 0; cidx < 4; cidx++)
                oc[j][cidx] = make_float4(0.f, 0.f, 0.f, 0.f);

        for (int n = nbeg; n < nend; n++) {
            const float4* vv4 = (const float4*)(sV + n * 16);
            float4 v0 = vv4[0], v1 = vv4[1], v2 = vv4[2], v3 = vv4[3];
#pragma unroll
            for (int j = 0; j < 4; j++) {
                float w = __expf(sS[(pg + 25 * j) * NN + n] - mx[j]);
                sum[j] += w;
                oc[j][0].x += w*v0.x; oc[j][0].y += w*v0.y; oc[j][0].z += w*v0.z; oc[j][0].w += w*v0.w;
                oc[j][1].x += w*v1.x; oc[j][1].y += w*v1.y; oc[j][1].z += w*v1.z; oc[j][1].w += w*v1.w;
                oc[j][2].x += w*v2.x; oc[j][2].y += w*v2.y; oc[j][2].z += w*v2.z; oc[j][2].w += w*v2.w;
                oc[j][3].x += w*v3.x; oc[j][3].y += w*v3.y; oc[j][3].z += w*v3.z; oc[j][3].w += w*v3.w;
            }
        }
#pragma unroll
        for (int j = 0; j < 4; j++) {
            sum[j] += __shfl_xor_sync(am, sum[j], 1);
            sum[j] += __shfl_xor_sync(am, sum[j], 2);
        }
#pragma unroll
        for (int j = 0; j < 4; j++)
#pragma unroll
            for (int cidx = 0; cidx < 4; cidx++) {
#pragma unroll
                for (int off = 1; off <= 2; off <<= 1) {
                    oc[j][cidx].x += __shfl_xor_sync(am, oc[j][cidx].x, off);
                    oc[j][cidx].y += __shfl_xor_sync(am, oc[j][cidx].y, off);
                    oc[j][cidx].z += __shfl_xor_sync(am, oc[j][cidx].z, off);
                    oc[j][cidx].w += __shfl_xor_sync(am, oc[j][cidx].w, off);
                }
            }

        if (qr == 0) {
#pragma unroll
            for (int j = 0; j < 4; j++) {
                float inv = 1.f / sum[j];
                float* ob = outc + ((size_t)b * PP + pg + 25 * j) * EE + h * 16;
#pragma unroll
                for (int cidx = 0; cidx < 4; cidx++) {
                    float4 o = oc[j][cidx];
                    o.x *= inv; o.y *= inv; o.z *= inv; o.w *= inv;
                    ((float4*)ob)[cidx] = o;
                }
            }
        }
    }
}

// ============================================================
// Routing: warp per token -> top2 of x@Wg + gate softmax
// ============================================================
__global__ void route_kernel(const float* __restrict__ x,
                             const float* __restrict__ Wg,
                             int* __restrict__ topi,
                             float* __restrict__ topg)
{
    const int wid = threadIdx.x >> 5, lane = threadIdx.x & 31;
    const int t = blockIdx.x * 8 + wid;
    if (t >= TT) return;
    float lg[8];
#pragma unroll
    for (int e = 0; e < 8; e++) lg[e] = 0.f;
    for (int f = lane; f < 256; f += 32) {
        float xv = x[(size_t)t * 256 + f];
        const float4* wg4 = (const float4*)&Wg[f * 8];
        float4 w0 = wg4[0], w1 = wg4[1];
        lg[0] += xv * w0.x; lg[1] += xv * w0.y; lg[2] += xv * w0.z; lg[3] += xv * w0.w;
        lg[4] += xv * w1.x; lg[5] += xv * w1.y; lg[6] += xv * w1.z; lg[7] += xv * w1.w;
    }
#pragma unroll
    for (int e = 0; e < 8; e++)
#pragma unroll
        for (int o = 16; o; o >>= 1) lg[e] += __shfl_xor_sync(~0u, lg[e], o);
    if (lane == 0) {
        float v1 = -1e30f, v2 = -1e30f; int i1 = 0, i2 = 0;
#pragma unroll
        for (int e = 0; e < 8; e++) {
            float vv = lg[e];
            if (vv > v1) { v2 = v1; i2 = i1; v1 = vv; i1 = e; }
            else if (vv > v2) { v2 = vv; i2 = e; }
        }
        float ex = expf(v2 - v1);
        float g1 = 1.f / (1.f + ex);
        topi[2 * t] = i1;  topi[2 * t + 1] = i2;
        topg[2 * t] = g1;  topg[2 * t + 1] = ex * g1;
    }
}

// ============================================================
// Per-expert token list via ballot scan (1024 threads, 25 chunks)
// ============================================================
__global__ __launch_bounds__(1024)
void build_lists_kernel(const int* __restrict__ topi,
                        int* __restrict__ list,
                        int* __restrict__ count)
{
    const int e = blockIdx.x;
    const int tid = threadIdx.x;
    const int wid = tid >> 5, lane = tid & 31;
    __shared__ int wtot[32];
    __shared__ int base;
    if (tid == 0) base = 0;
    __syncthreads();
    for (int c = 0; c < TT / 1024; c++) {
        int t = c * 1024 + tid;
        int slot = -1;
        int a = topi[2 * t], bq = topi[2 * t + 1];
        if (a == e) slot = 0; else if (bq == e) slot = 1;
        unsigned mask = __ballot_sync(0xffffffffu, slot >= 0);
        int wpre = __popc(mask & ((1u << lane) - 1));
        if (lane == 0) wtot[wid] = __popc(mask);
        __syncthreads();
        int wbase = 0, ctot = 0;
#pragma unroll
        for (int w = 0; w < 32; w++) {
            if (w < wid) wbase += wtot[w];
            ctot += wtot[w];
        }
        if (slot >= 0) list[e * TT + base + wbase + wpre] = t * 2 + slot;
        __syncthreads();
        if (tid == 0) base += ctot;
        __syncthreads();
    }
    if (tid == 0) count[e] = base;
}

// ============================================================
// Host launcher
// ============================================================
extern "C" void kernel_launch(void* const* d_in, const int* in_sizes, int n_in,
                              void* d_out, int out_size)
{
    const float* eln   = (const float*)d_in[0];
    const float* attr  = (const float*)d_in[1];
    const float* enc   = (const float*)d_in[2];
    const float* ninf  = (const float*)d_in[3];
    const float* bias  = (const float*)d_in[4];
    const float* bias1 = (const float*)d_in[5];
    const float* Wq    = (const float*)d_in[6];
    const float* Wk    = (const float*)d_in[7];
    const float* Wv    = (const float*)d_in[8];
    const float* Wg    = (const float*)d_in[9];
    const float* eW    = (const float*)d_in[10];
    const float* eb    = (const float*)d_in[11];
    float* out = (float*)d_out;

    float *pq, *pk, *pv, *patt, *pmh, *ptopg;
    int *ptopi, *plist, *pcount;
    cudaGetSymbolAddress((void**)&pq,    g_q);
    cudaGetSymbolAddress((void**)&pk,    g_k);
    cudaGetSymbolAddress((void**)&pv,    g_v);
    cudaGetSymbolAddress((void**)&patt,  g_att);
    cudaGetSymbolAddress((void**)&pmh,   g_mh);
    cudaGetSymbolAddress((void**)&ptopi, g_topi);
    cudaGetSymbolAddress((void**)&ptopg, g_topg);
    cudaGetSymbolAddress((void**)&plist, g_list);
    cudaGetSymbolAddress((void**)&pcount,g_count);

    const int attn_smem = (PP * NN + 2 * NN * 16) * 4;
    cudaFuncSetAttribute(attn_kernel,
        cudaFuncAttributeMaxDynamicSharedMemorySize, attn_smem);
    cudaFuncSetAttribute(gemm_bf16<0>,
        cudaFuncAttributeMaxDynamicSharedMemorySize, GEMM_SMEM);
    cudaFuncSetAttribute(gemm_bf16<1>,
        cudaFuncAttributeMaxDynamicSharedMemorySize, GEMM_SMEM);
    cudaFuncSetAttribute(gemm_bf16<2>,
        cudaFuncAttributeMaxDynamicSharedMemorySize, GEMM_SMEM);
    cudaFuncSetAttribute(gemm_bf16<3>,
        cudaFuncAttributeMaxDynamicSharedMemorySize, GEMM_SMEM);

    // q projection (bf16x3)
    gemm_bf16<1><<<dim3(TT / 128, 2), 256, GEMM_SMEM>>>(
        eln, attr, Wq, nullptr, pq, nullptr, TT, 260,
        nullptr, nullptr, nullptr, nullptr, nullptr, nullptr, nullptr);
    // fused k + v projections
    gemm_bf16<0><<<dim3(BB * NN / 128, 4), 256, GEMM_SMEM>>>(
        enc, nullptr, Wk, Wv, pk, pv, BB * NN, 256,
        nullptr, nullptr, nullptr, nullptr, nullptr, nullptr, nullptr);
    // attention (4-row quad sharing, fused softmax+PV)
    attn_kernel<<<dim3(BB, HH), 128, attn_smem>>>(pq, pk, pv, ninf, patt);
    // routing + lists
    route_kernel<<<TT / 8, 256>>>(patt, Wg, ptopi, ptopg);
    build_lists_kernel<<<NE, 1024>>>(ptopi, plist, pcount);
    // gathered expert GEMM, gate+bias fused
    gemm_bf16<2><<<dim3(TT / 128, 2, NE), 256, GEMM_SMEM>>>(
        patt, nullptr, eW, nullptr, pmh, nullptr, TT, 256,
        plist, pcount, ptopg, eb, nullptr, nullptr, nullptr);
    // pointer-score GEMM with fused bias/tanh/ninf + output softmax
    gemm_bf16<3><<<dim3(1, 1, BB), 256, GEMM_SMEM>>>(
        pmh, nullptr, enc, nullptr, out, nullptr, PP, 256,
        nullptr, nullptr, nullptr, nullptr, bias, bias1, ninf);
}

// round 15
// speedup vs baseline: 1.1299x; 1.1299x over previous
#include <cuda_runtime.h>
#include <cuda_bf16.h>
#include <cstdint>
#include <cstddef>

// ---------------- problem constants ----------------
#define BB   256
#define PP   100
#define NN   101
#define EE   256
#define HH   16
#define NE   8
#define TT   (BB*PP)

// ---------------- scratch ----------------
__device__ float g_q  [TT    * EE];
__device__ float g_k  [BB*NN * EE];
__device__ float g_v  [BB*NN * EE];
__device__ float g_att[TT    * EE];
__device__ float g_mh [2*TT  * EE];
__device__ int   g_topi[TT * 2];
__device__ float g_topg[TT * 2];
__device__ int   g_list[NE * TT];
__device__ int   g_count[NE];

// ---------------- bf16 split helpers ----------------
__device__ __forceinline__ void splitpack(float x0, float x1,
                                          uint32_t& h, uint32_t& l)
{
    __nv_bfloat162 hb = __floats2bfloat162_rn(x0, x1);
    float r0 = x0 - __bfloat162float(hb.x);
    float r1 = x1 - __bfloat162float(hb.y);
    __nv_bfloat162 lb = __floats2bfloat162_rn(r0, r1);
    h = *reinterpret_cast<uint32_t*>(&hb);
    l = *reinterpret_cast<uint32_t*>(&lb);
}
__device__ __forceinline__ void mma16(float c[4],
    uint32_t a0, uint32_t a1, uint32_t a2, uint32_t a3,
    uint32_t b0, uint32_t b1)
{
    asm volatile(
        "mma.sync.aligned.m16n8k16.row.col.f32.bf16.bf16.f32 "
        "{%0,%1,%2,%3}, {%4,%5,%6,%7}, {%8,%9}, {%0,%1,%2,%3};"
        : "+f"(c[0]), "+f"(c[1]), "+f"(c[2]), "+f"(c[3])
        : "r"(a0), "r"(a1), "r"(a2), "r"(a3), "r"(b0), "r"(b1));
}

// ============================================================
// bf16x3 GEMM: 128x128 tile, BK=16, 256 threads (8 warps 2x4),
// warp tile 64x32, pitch-12 packed smem, 2-stage double buffer.
// MODE 0: fused k/v proj: y<2 -> Wk->g_k, y>=2 -> Wv->g_v
// MODE 1: q proj, A = concat(eln, attr), K=260
// MODE 2: gathered expert GEMM + gate/bias epilogue
// MODE 3: per-batch pointer scores + bias/tanh/ninf + FUSED
//         output softmax (scores staged in smem) -> d_out
// ============================================================
#define PLANE 1536               // 128 rows * 12 uint32
#define GEMM_SMEM (8 * PLANE * 4 + 1536)
#define SCP 104                  // score buffer pitch (floats)

template<int MODE>
__launch_bounds__(256, 2)
__global__ void gemm_bf16(const float* __restrict__ A,
                          const float* __restrict__ A2,
                          const float* __restrict__ Bm,
                          const float* __restrict__ Bm2,
                          float* __restrict__ Cout,
                          float* __restrict__ Cout2,
                          int M, int K,
                          const int*   __restrict__ list,
                          const int*   __restrict__ count,
                          const float* __restrict__ topg,
                          const float* __restrict__ eb,
                          const float* __restrict__ bias,
                          const float* __restrict__ bias1,
                          const float* __restrict__ ninf)
{
    extern __shared__ uint32_t smemu[];
    uint32_t* Ah = smemu;                // 2 stages x PLANE
    uint32_t* Al = Ah + 2 * PLANE;
    uint32_t* Bh = Al + 2 * PLANE;
    uint32_t* Bl = Bh + 2 * PLANE;
    int*    s_tok  = (int*)  (Bl + 2 * PLANE);
    float*  s_gate = (float*)(s_tok + 128);
    int*    s_slot = (int*)  (s_gate + 128);
    float*  sScore = (float*)smemu;      // MODE 3: reused after mainloop

    const int tid = threadIdx.x;
    const int m0 = blockIdx.x * 128;
    const int bz = blockIdx.z;

    int n0;
    const float* Aro = A;
    const float* Bro;
    float* Co;
    int e = 0;

    if (MODE == 0) {
        int y = blockIdx.y;
        Bro = (y < 2) ? Bm : Bm2;
        Co  = (y < 2) ? Cout : Cout2;
        n0  = (y & 1) * 128;
    } else {
        Bro = Bm; Co = Cout;
        n0 = blockIdx.y * 128;
    }
    if (MODE == 2) {
        e = bz;
        int cnt = count[e];
        if (m0 >= cnt) return;
        Bro = Bm + (size_t)e * 65536;
        if (tid < 128) {
            int r = m0 + tid;
            if (r < cnt) {
                int entry = list[e * TT + r];
                s_tok[tid]  = entry >> 1;
                s_slot[tid] = entry & 1;
                s_gate[tid] = topg[entry];
            } else s_tok[tid] = -1;
        }
        __syncthreads();
    }
    if (MODE == 3) {
        Aro = A  + (size_t)bz * PP * EE;
        Bro = Bm + (size_t)bz * NN * EE;
    }

    const int NT = (MODE == 1) ? 17 : 16;

    const int wid = tid >> 5, lane = tid & 31;
    const int wm = wid & 1;
    const int wn = wid >> 1;
    const int g  = lane >> 2;
    const int tg = lane & 3;

    const int amA[2] = { (0*256 + tid) >> 2, (1*256 + tid) >> 2 };
    const int akc    = tid & 3;
    const int akA    = akc * 4;
    const int bn [2] = { (0*256 + tid) & 127, (1*256 + tid) & 127 };
    const int bkq[2] = { (0*256 + tid) >> 7,  (1*256 + tid) >> 7 };

    float4 av[2], bv[2];

    auto loadA = [&](int k0) {
#pragma unroll
        for (int it = 0; it < 2; it++) {
            int m = amA[it];
            int kg = k0 + akA;
            float4 v = make_float4(0.f, 0.f, 0.f, 0.f);
            if (MODE == 1) {
                if (kg < 256)       v = *(const float4*)(Aro + (size_t)(m0 + m) * 256 + kg);
                else if (kg == 256) v = *(const float4*)(A2 + (size_t)(m0 + m) * 4);
            } else if (MODE == 2) {
                int t = s_tok[m];
                if (t >= 0) v = *(const float4*)(Aro + (size_t)t * 256 + kg);
            } else if (MODE == 3) {
                if (m < PP) {
                    float4 x = *(const float4*)(Aro + (size_t)m * 256 + kg);
                    float4 y = *(const float4*)(Aro + (size_t)TT * EE + (size_t)m * 256 + kg);
                    v = make_float4(x.x + y.x, x.y + y.y, x.z + y.z, x.w + y.w);
                }
            } else {
                v = *(const float4*)(Aro + (size_t)(m0 + m) * 256 + kg);
            }
            av[it] = v;
        }
    };
    auto loadB = [&](int k0) {
#pragma unroll
        for (int it = 0; it < 2; it++) {
            int n = bn[it], kq = bkq[it];
            if (MODE == 3) {
                bv[it] = (n < NN)
                    ? *(const float4*)(Bro + (size_t)n * 256 + k0 + kq * 4)
                    : make_float4(0.f, 0.f, 0.f, 0.f);
            } else {
                float vv[4];
#pragma unroll
                for (int i = 0; i < 4; i++) {
                    int kg = k0 + kq * 4 + i;
                    vv[i] = (kg < K) ? Bro[(size_t)kg * 256 + n0 + n] : 0.f;
                }
                bv[it] = make_float4(vv[0], vv[1], vv[2], vv[3]);
            }
        }
    };
    auto storeTile = [&](int stg) {
        uint32_t* Ahs = Ah + stg * PLANE;
        uint32_t* Als = Al + stg * PLANE;
        uint32_t* Bhs = Bh + stg * PLANE;
        uint32_t* Bls = Bl + stg * PLANE;
#pragma unroll
        for (int it = 0; it < 2; it++) {
            uint32_t h01, l01, h23, l23;
            splitpack(av[it].x, av[it].y, h01, l01);
            splitpack(av[it].z, av[it].w, h23, l23);
            int idx = amA[it] * 12 + akc * 2;
            *(uint2*)&Ahs[idx] = make_uint2(h01, h23);
            *(uint2*)&Als[idx] = make_uint2(l01, l23);
        }
#pragma unroll
        for (int it = 0; it < 2; it++) {
            uint32_t h01, l01, h23, l23;
            splitpack(bv[it].x, bv[it].y, h01, l01);
            splitpack(bv[it].z, bv[it].w, h23, l23);
            int idx = bn[it] * 12 + bkq[it] * 2;
            *(uint2*)&Bhs[idx] = make_uint2(h01, h23);
            *(uint2*)&Bls[idx] = make_uint2(l01, l23);
        }
    };

    float c[4][4][4];
#pragma unroll
    for (int mt = 0; mt < 4; mt++)
#pragma unroll
        for (int nt = 0; nt < 4; nt++)
#pragma unroll
            for (int j = 0; j < 4; j++) c[mt][nt][j] = 0.f;

    loadA(0); loadB(0);
    storeTile(0);
    __syncthreads();

    int cur = 0;
    for (int t = 0; t < NT; t++) {
        if (t + 1 < NT) { loadA((t + 1) * 16); loadB((t + 1) * 16); }

        const uint32_t* Ach = Ah + cur * PLANE;
        const uint32_t* Acl = Al + cur * PLANE;
        const uint32_t* Bch = Bh + cur * PLANE;
        const uint32_t* Bcl = Bl + cur * PLANE;

        uint32_t bhf[4][2], blf[4][2];
#pragma unroll
        for (int nt = 0; nt < 4; nt++) {
            int n = wn * 32 + nt * 8 + g;
            bhf[nt][0] = Bch[n * 12 + tg];
            bhf[nt][1] = Bch[n * 12 + tg + 4];
            blf[nt][0] = Bcl[n * 12 + tg];
            blf[nt][1] = Bcl[n * 12 + tg + 4];
        }
#pragma unroll
        for (int mt = 0; mt < 4; mt++) {
            int r0 = (wm * 64 + mt * 16 + g) * 12;
            int r1 = r0 + 8 * 12;
            uint32_t ah0 = Ach[r0 + tg],     ah1 = Ach[r1 + tg];
            uint32_t ah2 = Ach[r0 + tg + 4], ah3 = Ach[r1 + tg + 4];
            uint32_t al0 = Acl[r0 + tg],     al1 = Acl[r1 + tg];
            uint32_t al2 = Acl[r0 + tg + 4], al3 = Acl[r1 + tg + 4];
#pragma unroll
            for (int nt = 0; nt < 4; nt++)
                mma16(c[mt][nt], ah0, ah1, ah2, ah3, bhf[nt][0], bhf[nt][1]);
#pragma unroll
            for (int nt = 0; nt < 4; nt++)
                mma16(c[mt][nt], al0, al1, al2, al3, bhf[nt][0], bhf[nt][1]);
#pragma unroll
            for (int nt = 0; nt < 4; nt++)
                mma16(c[mt][nt], ah0, ah1, ah2, ah3, blf[nt][0], blf[nt][1]);
        }
        if (t + 1 < NT) {
            storeTile(cur ^ 1);
            __syncthreads();
            cur ^= 1;
        }
    }

    if (MODE == 3) __syncthreads();   // smem about to be reused for scores

    // ---------- epilogue ----------
#pragma unroll
    for (int mt = 0; mt < 4; mt++) {
#pragma unroll
        for (int nt = 0; nt < 4; nt++) {
            int ml = wm * 64 + mt * 16 + g;
            int nl = wn * 32 + nt * 8 + tg * 2;
#pragma unroll
            for (int half = 0; half < 2; half++) {
                int row = ml + half * 8;
                float v0 = c[mt][nt][half * 2 + 0];
                float v1 = c[mt][nt][half * 2 + 1];
                if (MODE <= 1) {
                    *(float2*)(Co + (size_t)(m0 + row) * 256 + n0 + nl) =
                        make_float2(v0, v1);
                } else if (MODE == 2) {
                    int t = s_tok[row];
                    if (t >= 0) {
                        float gate = s_gate[row];
                        const float* bb = eb + e * 256 + n0 + nl;
                        *(float2*)(Co + (size_t)s_slot[row] * TT * EE +
                                   (size_t)t * 256 + n0 + nl) =
                            make_float2(gate * (v0 + bb[0]), gate * (v1 + bb[1]));
                    }
                } else {
                    if (row < PP) {
#pragma unroll
                        for (int j = 0; j < 2; j++) {
                            int col = nl + j;
                            if (col < NN) {
                                size_t off = (size_t)bz * PP * NN + (size_t)row * NN + col;
                                float s = (j ? v1 : v0) + bias[off] + bias1[off];
                                s = 10.f * tanhf(s * 0.0625f);
                                sScore[row * SCP + col] = s + ninf[off];
                            }
                        }
                    }
                }
            }
        }
    }

    // ---------- MODE 3: fused output softmax ----------
    if (MODE == 3) {
        __syncthreads();
        float* outb = Co + (size_t)bz * PP * NN;
        for (int r = wid; r < PP; r += 8) {
            const float* srow = sScore + r * SCP;
            float vals[4];
            float mx = -1e30f;
#pragma unroll
            for (int i = 0; i < 4; i++) {
                int n = lane + i * 32;
                vals[i] = (n < NN) ? srow[n] : -1e30f;
                mx = fmaxf(mx, vals[i]);
            }
#pragma unroll
            for (int o = 16; o; o >>= 1) mx = fmaxf(mx, __shfl_xor_sync(~0u, mx, o));
            float sum = 0.f;
#pragma unroll
            for (int i = 0; i < 4; i++) {
                vals[i] = __expf(vals[i] - mx);
                sum += vals[i];
            }
#pragma unroll
            for (int o = 16; o; o >>= 1) sum += __shfl_xor_sync(~0u, sum, o);
            float inv = 1.f / sum;
#pragma unroll
            for (int i = 0; i < 4; i++) {
                int n = lane + i * 32;
                if (n < NN) outb[r * NN + n] = vals[i] * inv;
            }
        }
    }
}

// ============================================================
// Attention: block (b,h), 128 threads. Thread owns TWO rows
// (p, p+50); pair of threads splits the n loop. Fused softmax:
// exp+sum merged into PV pass. (R13 version, measured best)
// ============================================================
__global__ __launch_bounds__(128)
void attn_kernel(const float* __restrict__ q,
                 const float* __restrict__ k,
                 const float* __restrict__ v,
                 const float* __restrict__ ninf,
                 float* __restrict__ outc)
{
    extern __shared__ float sm[];
    float* sS = sm;                  // 10100
    float* sK = sm + 10100;          // 1616
    float* sV = sm + 10100 + 1616;   // 1616
    const int b = blockIdx.x, h = blockIdx.y;
    const int tid = threadIdx.x;

    const float4* nf4 = (const float4*)(ninf + (size_t)b * PP * NN);
    float4* sS4 = (float4*)sS;
    for (int i = tid; i < PP * NN / 4; i += 128) sS4[i] = nf4[i];

    const float* kb = k + (size_t)b * NN * EE + h * 16;
    const float* vb = v + (size_t)b * NN * EE + h * 16;
    for (int i = tid; i < NN * 4; i += 128) {
        int n = i >> 2, c = i & 3;
        *(float4*)(sK + n * 16 + c * 4) = *(const float4*)(kb + (size_t)n * EE + c * 4);
        *(float4*)(sV + n * 16 + c * 4) = *(const float4*)(vb + (size_t)n * EE + c * 4);
    }
    __syncthreads();

    const int pr = tid >> 1, half = tid & 1;
    if (pr < 50) {
        unsigned am = __activemask();
        const int r0 = pr, r1 = pr + 50;
        const float* q0p = q + ((size_t)b * PP + r0) * EE + h * 16;
        const float* q1p = q + ((size_t)b * PP + r1) * EE + h * 16;
        float4 qa0 = ((const float4*)q0p)[0], qa1 = ((const float4*)q0p)[1];
        float4 qa2 = ((const float4*)q0p)[2], qa3 = ((const float4*)q0p)[3];
        float4 qb0 = ((const float4*)q1p)[0], qb1 = ((const float4*)q1p)[1];
        float4 qb2 = ((const float4*)q1p)[2], qb3 = ((const float4*)q1p)[3];

        const int nbeg = half ? 51 : 0;
        const int nend = half ? NN : 51;
        float* row0 = sS + r0 * NN;
        float* row1 = sS + r1 * NN;

        // pass 1: scores + max
        float mx0 = -1e30f, mx1 = -1e30f;
        for (int n = nbeg; n < nend; n++) {
            const float4* kk4 = (const float4*)(sK + n * 16);
            float4 k0 = kk4[0], k1 = kk4[1], k2 = kk4[2], k3 = kk4[3];
            float sa = qa0.x*k0.x + qa0.y*k0.y + qa0.z*k0.z + qa0.w*k0.w
                     + qa1.x*k1.x + qa1.y*k1.y + qa1.z*k1.z + qa1.w*k1.w
                     + qa2.x*k2.x + qa2.y*k2.y + qa2.z*k2.z + qa2.w*k2.w
                     + qa3.x*k3.x + qa3.y*k3.y + qa3.z*k3.z + qa3.w*k3.w;
            float sb = qb0.x*k0.x + qb0.y*k0.y + qb0.z*k0.z + qb0.w*k0.w
                     + qb1.x*k1.x + qb1.y*k1.y + qb1.z*k1.z + qb1.w*k1.w
                     + qb2.x*k2.x + qb2.y*k2.y + qb2.z*k2.z + qb2.w*k2.w
                     + qb3.x*k3.x + qb3.y*k3.y + qb3.z*k3.z + qb3.w*k3.w;
            float v0 = sa * 0.25f + row0[n];
            float v1 = sb * 0.25f + row1[n];
            row0[n] = v0; row1[n] = v1;
            mx0 = fmaxf(mx0, v0); mx1 = fmaxf(mx1, v1);
        }
        mx0 = fmaxf(mx0, __shfl_xor_sync(am, mx0, 1));
        mx1 = fmaxf(mx1, __shfl_xor_sync(am, mx1, 1));

        // pass 2 (fused): exp + sum + PV accumulate
        float sum0 = 0.f, sum1 = 0.f;
        float4 oa0 = {0,0,0,0}, oa1 = {0,0,0,0}, oa2 = {0,0,0,0}, oa3 = {0,0,0,0};
        float4 ob0 = {0,0,0,0}, ob1 = {0,0,0,0}, ob2 = {0,0,0,0}, ob3 = {0,0,0,0};
        for (int n = nbeg; n < nend; n++) {
            float w0 = __expf(row0[n] - mx0);
            float w1 = __expf(row1[n] - mx1);
            sum0 += w0; sum1 += w1;
            const float4* vv4 = (const float4*)(sV + n * 16);
            float4 v0 = vv4[0], v1 = vv4[1], v2 = vv4[2], v3 = vv4[3];
            oa0.x += w0*v0.x; oa0.y += w0*v0.y; oa0.z += w0*v0.z; oa0.w += w0*v0.w;
            oa1.x += w0*v1.x; oa1.y += w0*v1.y; oa1.z += w0*v1.z; oa1.w += w0*v1.w;
            oa2.x += w0*v2.x; oa2.y += w0*v2.y; oa2.z += w0*v2.z; oa2.w += w0*v2.w;
            oa3.x += w0*v3.x; oa3.y += w0*v3.y; oa3.z += w0*v3.z; oa3.w += w0*v3.w;
            ob0.x += w1*v0.x; ob0.y += w1*v0.y; ob0.z += w1*v0.z; ob0.w += w1*v0.w;
            ob1.x += w1*v1.x; ob1.y += w1*v1.y; ob1.z += w1*v1.z; ob1.w += w1*v1.w;
            ob2.x += w1*v2.x; ob2.y += w1*v2.y; ob2.z += w1*v2.z; ob2.w += w1*v2.w;
            ob3.x += w1*v3.x; ob3.y += w1*v3.y; ob3.z += w1*v3.z; ob3.w += w1*v3.w;
        }
        sum0 += __shfl_xor_sync(am, sum0, 1);
        sum1 += __shfl_xor_sync(am, sum1, 1);
        float inv0 = 1.f / sum0, inv1 = 1.f / sum1;

#define RED4(o) \
        o.x += __shfl_xor_sync(am, o.x, 1); o.y += __shfl_xor_sync(am, o.y, 1); \
        o.z += __shfl_xor_sync(am, o.z, 1); o.w += __shfl_xor_sync(am, o.w, 1);
        RED4(oa0) RED4(oa1) RED4(oa2) RED4(oa3)
        RED4(ob0) RED4(ob1) RED4(ob2) RED4(ob3)
#undef RED4

        if (half == 0) {
            float* o0p = outc + ((size_t)b * PP + r0) * EE + h * 16;
            float* o1p = outc + ((size_t)b * PP + r1) * EE + h * 16;
            oa0.x*=inv0; oa0.y*=inv0; oa0.z*=inv0; oa0.w*=inv0;
            oa1.x*=inv0; oa1.y*=inv0; oa1.z*=inv0; oa1.w*=inv0;
            oa2.x*=inv0; oa2.y*=inv0; oa2.z*=inv0; oa2.w*=inv0;
            oa3.x*=inv0; oa3.y*=inv0; oa3.z*=inv0; oa3.w*=inv0;
            ob0.x*=inv1; ob0.y*=inv1; ob0.z*=inv1; ob0.w*=inv1;
            ob1.x*=inv1; ob1.y*=inv1; ob1.z*=inv1; ob1.w*=inv1;
            ob2.x*=inv1; ob2.y*=inv1; ob2.z*=inv1; ob2.w*=inv1;
            ob3.x*=inv1; ob3.y*=inv1; ob3.z*=inv1; ob3.w*=inv1;
            ((float4*)o0p)[0] = oa0; ((float4*)o0p)[1] = oa1;
            ((float4*)o0p)[2] = oa2; ((float4*)o0p)[3] = oa3;
            ((float4*)o1p)[0] = ob0; ((float4*)o1p)[1] = ob1;
            ((float4*)o1p)[2] = ob2; ((float4*)o1p)[3] = ob3;
        }
    }
}

// ============================================================
// Routing: warp per token -> top2 of x@Wg + gate softmax
// ============================================================
__global__ void route_kernel(const float* __restrict__ x,
                             const float* __restrict__ Wg,
                             int* __restrict__ topi,
                             float* __restrict__ topg)
{
    const int wid = threadIdx.x >> 5, lane = threadIdx.x & 31;
    const int t = blockIdx.x * 8 + wid;
    if (t >= TT) return;
    float lg[8];
#pragma unroll
    for (int e = 0; e < 8; e++) lg[e] = 0.f;
    for (int f = lane; f < 256; f += 32) {
        float xv = x[(size_t)t * 256 + f];
        const float4* wg4 = (const float4*)&Wg[f * 8];
        float4 w0 = wg4[0], w1 = wg4[1];
        lg[0] += xv * w0.x; lg[1] += xv * w0.y; lg[2] += xv * w0.z; lg[3] += xv * w0.w;
        lg[4] += xv * w1.x; lg[5] += xv * w1.y; lg[6] += xv * w1.z; lg[7] += xv * w1.w;
    }
#pragma unroll
    for (int e = 0; e < 8; e++)
#pragma unroll
        for (int o = 16; o; o >>= 1) lg[e] += __shfl_xor_sync(~0u, lg[e], o);
    if (lane == 0) {
        float v1 = -1e30f, v2 = -1e30f; int i1 = 0, i2 = 0;
#pragma unroll
        for (int e = 0; e < 8; e++) {
            float vv = lg[e];
            if (vv > v1) { v2 = v1; i2 = i1; v1 = vv; i1 = e; }
            else if (vv > v2) { v2 = vv; i2 = e; }
        }
        float ex = expf(v2 - v1);
        float g1 = 1.f / (1.f + ex);
        topi[2 * t] = i1;  topi[2 * t + 1] = i2;
        topg[2 * t] = g1;  topg[2 * t + 1] = ex * g1;
    }
}

// ============================================================
// Per-expert token list via ballot scan (1024 threads, 25 chunks)
// ============================================================
__global__ __launch_bounds__(1024)
void build_lists_kernel(const int* __restrict__ topi,
                        int* __restrict__ list,
                        int* __restrict__ count)
{
    const int e = blockIdx.x;
    const int tid = threadIdx.x;
    const int wid = tid >> 5, lane = tid & 31;
    __shared__ int wtot[32];
    __shared__ int base;
    if (tid == 0) base = 0;
    __syncthreads();
    for (int c = 0; c < TT / 1024; c++) {
        int t = c * 1024 + tid;
        int slot = -1;
        int a = topi[2 * t], bq = topi[2 * t + 1];
        if (a == e) slot = 0; else if (bq == e) slot = 1;
        unsigned mask = __ballot_sync(0xffffffffu, slot >= 0);
        int wpre = __popc(mask & ((1u << lane) - 1));
        if (lane == 0) wtot[wid] = __popc(mask);
        __syncthreads();
        int wbase = 0, ctot = 0;
#pragma unroll
        for (int w = 0; w < 32; w++) {
            if (w < wid) wbase += wtot[w];
            ctot += wtot[w];
        }
        if (slot >= 0) list[e * TT + base + wbase + wpre] = t * 2 + slot;
        __syncthreads();
        if (tid == 0) base += ctot;
        __syncthreads();
    }
    if (tid == 0) count[e] = base;
}

// ============================================================
// Host launcher
// ============================================================
extern "C" void kernel_launch(void* const* d_in, const int* in_sizes, int n_in,
                              void* d_out, int out_size)
{
    const float* eln   = (const float*)d_in[0];
    const float* attr  = (const float*)d_in[1];
    const float* enc   = (const float*)d_in[2];
    const float* ninf  = (const float*)d_in[3];
    const float* bias  = (const float*)d_in[4];
    const float* bias1 = (const float*)d_in[5];
    const float* Wq    = (const float*)d_in[6];
    const float* Wk    = (const float*)d_in[7];
    const float* Wv    = (const float*)d_in[8];
    const float* Wg    = (const float*)d_in[9];
    const float* eW    = (const float*)d_in[10];
    const float* eb    = (const float*)d_in[11];
    float* out = (float*)d_out;

    float *pq, *pk, *pv, *patt, *pmh, *ptopg;
    int *ptopi, *plist, *pcount;
    cudaGetSymbolAddress((void**)&pq,    g_q);
    cudaGetSymbolAddress((void**)&pk,    g_k);
    cudaGetSymbolAddress((void**)&pv,    g_v);
    cudaGetSymbolAddress((void**)&patt,  g_att);
    cudaGetSymbolAddress((void**)&pmh,   g_mh);
    cudaGetSymbolAddress((void**)&ptopi, g_topi);
    cudaGetSymbolAddress((void**)&ptopg, g_topg);
    cudaGetSymbolAddress((void**)&plist, g_list);
    cudaGetSymbolAddress((void**)&pcount,g_count);

    const int attn_smem = (PP * NN + 2 * NN * 16) * 4;
    cudaFuncSetAttribute(attn_kernel,
        cudaFuncAttributeMaxDynamicSharedMemorySize, attn_smem);
    cudaFuncSetAttribute(gemm_bf16<0>,
        cudaFuncAttributeMaxDynamicSharedMemorySize, GEMM_SMEM);
    cudaFuncSetAttribute(gemm_bf16<1>,
        cudaFuncAttributeMaxDynamicSharedMemorySize, GEMM_SMEM);
    cudaFuncSetAttribute(gemm_bf16<2>,
        cudaFuncAttributeMaxDynamicSharedMemorySize, GEMM_SMEM);
    cudaFuncSetAttribute(gemm_bf16<3>,
        cudaFuncAttributeMaxDynamicSharedMemorySize, GEMM_SMEM);

    // q projection (bf16x3)
    gemm_bf16<1><<<dim3(TT / 128, 2), 256, GEMM_SMEM>>>(
        eln, attr, Wq, nullptr, pq, nullptr, TT, 260,
        nullptr, nullptr, nullptr, nullptr, nullptr, nullptr, nullptr);
    // fused k + v projections
    gemm_bf16<0><<<dim3(BB * NN / 128, 4), 256, GEMM_SMEM>>>(
        enc, nullptr, Wk, Wv, pk, pv, BB * NN, 256,
        nullptr, nullptr, nullptr, nullptr, nullptr, nullptr, nullptr);
    // attention (R13: 2-row pair, fused softmax+PV)
    attn_kernel<<<dim3(BB, HH), 128, attn_smem>>>(pq, pk, pv, ninf, patt);
    // routing + lists
    route_kernel<<<TT / 8, 256>>>(patt, Wg, ptopi, ptopg);
    build_lists_kernel<<<NE, 1024>>>(ptopi, plist, pcount);
    // gathered expert GEMM, gate+bias fused
    gemm_bf16<2><<<dim3(TT / 128, 2, NE), 256, GEMM_SMEM>>>(
        patt, nullptr, eW, nullptr, pmh, nullptr, TT, 256,
        plist, pcount, ptopg, eb, nullptr, nullptr, nullptr);
    // pointer-score GEMM with fused bias/tanh/ninf + output softmax
    gemm_bf16<3><<<dim3(1, 1, BB), 256, GEMM_SMEM>>>(
        pmh, nullptr, enc, nullptr, out, nullptr, PP, 256,
        nullptr, nullptr, nullptr, nullptr, bias, bias1, ninf);
}